// round 17
// baseline (speedup 1.0000x reference)
#include <cuda_runtime.h>

#define V_NODES 2048
#define D_F     128
#define NBLK    128            // scatter blocks
#define NPB     16             // nodes per scatter block
#define NK      73             // output coefficient rows (1 + 8 + 64)
#define NKU     45             // unique rows (1 + 8 + 36 triangle)
#define NOUT    (NK * D_F)     // 9344
#define RED_IBLK 37            // ceil(NOUT/256)
#define RED_SLICES 16          // reduce slices (8 partials each)
#define TILES   16             // 2048 / 128 tile bands
#define NTRI    136            // upper-triangle tile count

// Scratch (static device globals — no allocation allowed)
__device__ float g_rcs[TILES][TILES][128];     // band sums: deg_a = sum_tj g_rcs[ti][tj][r]
__device__ float g_partial[NBLK * NKU * D_F];  // block-major unique-row partials (3 MB)

// ---------------------------------------------------------------------------
// Kernel 1: degree band-sums from the UPPER TRIANGLE of 128x128 tiles only
// (W symmetric: each tile yields row-sums for band ti and col-sums for band
// tj). 136 blocks x 512 threads, 8 batched LDG.128 per warp-row. Blocks
// 0..36 also zero the output buffer (ordered before reduce's atomics by the
// two kernel boundaries).
// ---------------------------------------------------------------------------
__global__ void __launch_bounds__(512) deg_tile_kernel(const float* __restrict__ W,
                                                       float* __restrict__ out) {
    __shared__ float rs_sh[128];
    __shared__ float cs_sh[16][132];   // padded stride kills bank conflicts

    const int tid = threadIdx.x;
    if (blockIdx.x < RED_IBLK) {
        int i = blockIdx.x * 512 + tid;
        if (i < NOUT) out[i] = 0.f;
    }

    // map blockIdx -> (ti, tj), ti <= tj
    int rem = blockIdx.x, ti = 0;
    while (rem >= TILES - ti) { rem -= TILES - ti; ti++; }
    const int tj = ti + rem;

    const int w = tid >> 5;
    const int l = tid & 31;

    const float4* base = (const float4*)W + (size_t)(ti * 128) * 512 + tj * 32 + l;

    float4 v[8];
#pragma unroll
    for (int k = 0; k < 8; k++)
        v[k] = base[(size_t)(w + 16 * k) * 512];

    float cx = 0.f, cy = 0.f, cz = 0.f, cw = 0.f;
#pragma unroll
    for (int k = 0; k < 8; k++) {
        float4 t = v[k];
        cx += t.x; cy += t.y; cz += t.z; cw += t.w;
        float rsum = (t.x + t.y) + (t.z + t.w);
#pragma unroll
        for (int off = 16; off; off >>= 1)
            rsum += __shfl_down_sync(0xffffffffu, rsum, off);
        if (l == 0) rs_sh[w + 16 * k] = rsum;
    }
    cs_sh[w][l * 4 + 0] = cx;
    cs_sh[w][l * 4 + 1] = cy;
    cs_sh[w][l * 4 + 2] = cz;
    cs_sh[w][l * 4 + 3] = cw;
    __syncthreads();

    if (tid < 128) {
        g_rcs[ti][tj][tid] = rs_sh[tid];
        if (ti != tj) {
            float s = 0.f;
#pragma unroll
            for (int k = 0; k < 16; k++)
                s += cs_sh[k][tid];
            g_rcs[tj][ti][tid] = s;
        }
    }
}

// ---------------------------------------------------------------------------
// Kernel 2: scattering with UNIQUE accumulators (layer-2 is symmetric in
// (j1,j2), so only the 36 lo<=hi pairs are computed/stored). 128 blocks x
// 256 threads; thread = (half, d); half handles 8 nodes. No barrier, no
// in-kernel reduce — partials go to g_partial[128][45][128].
// ---------------------------------------------------------------------------
__global__ void __launch_bounds__(256) scat_kernel(const float* __restrict__ f) {
    __shared__ float lam_s[8][NPB];
    __shared__ float degp_sh[16][NPB];
    __shared__ float deg_sh[NPB];
    __shared__ float comb[NKU][D_F];

    const int b = blockIdx.x;
    const int tid = threadIdx.x;
    const int half = tid >> 7;
    const int d = tid & 127;

    // --- coalesced degree finalize: 16 band contributions per node ---
    {
        const int c  = tid & 15;
        const int tj = tid >> 4;
        const int ti = b >> 3;
        const int r  = (b & 7) * 16 + c;
        degp_sh[tj][c] = g_rcs[ti][tj][r];
    }
    __syncthreads();
    if (tid < NPB) {
        float s = 0.f;
#pragma unroll
        for (int k = 0; k < 16; k++)
            s += degp_sh[k][tid];
        deg_sh[tid] = s;
    }
    __syncthreads();

    if (tid < NPB) {
        float dg = deg_sh[tid];
        float inv = 1.0f / fmaxf(1.0f, dg);       // dhalf^2 with clamp
        float E = fabsf(dg * inv);                // |eigenvalue| for this node
        float logE = logf(E);
        const float Ac = 0.34657359027997264f;    // A = 3*ln(2)/6
        float s = 1.125f;                         // (R/2)*sum(d^2) + (R/2)*d0^2
#pragma unroll
        for (int j = 2; j <= 8; j++) {
            float x = logE - Ac * (float)(j - 1) * (1.0f / 3.0f);
            float w = 0.0f;
            if (x > -Ac && x <= 0.0f)
                w = 0.5f - 0.5f * cosf(x * (6.283185307179586f / Ac));
            lam_s[j - 1][tid] = w;
            s -= w * w;
        }
        lam_s[0][tid] = sqrtf(fmaxf(s, 0.0f));    // scaling function
    }
    __syncthreads();

    const int n0 = half * 8;
    float fv[8];
#pragma unroll
    for (int n = 0; n < 8; n++)
        fv[n] = f[(size_t)(b * NPB + n0 + n) * D_F + d];

    float acc[NKU];
#pragma unroll
    for (int k = 0; k < NKU; k++) acc[k] = 0.f;

#pragma unroll
    for (int n = 0; n < 8; n++) {
        float v = fv[n];
        float af = fabsf(v);
        acc[0] += v;
        float l[8];
#pragma unroll
        for (int j = 0; j < 8; j++) l[j] = lam_s[j][n0 + n];   // smem broadcast
#pragma unroll
        for (int j = 0; j < 8; j++) acc[1 + j] += l[j] * af;
        int idx = 9;
#pragma unroll
        for (int lo = 0; lo < 8; lo++) {
            float t = l[lo] * af;
#pragma unroll
            for (int hi = lo; hi < 8; hi++)
                acc[idx++] += l[hi] * t;
        }
    }

    // Combine halves through smem, half 1 stores this block's partials.
    if (half == 0) {
#pragma unroll
        for (int k = 0; k < NKU; k++) comb[k][d] = acc[k];
    }
    __syncthreads();
    if (half == 1) {
        float* p = g_partial + (size_t)b * (NKU * D_F) + d;
#pragma unroll
        for (int k = 0; k < NKU; k++)
            p[k * D_F] = acc[k] + comb[k][d];
    }
}

// ---------------------------------------------------------------------------
// Kernel 3: reduce 128 partials per unique row into the 73-row output.
// 16 slices x 37 i-blocks = 592 blocks; each thread sums 8 partials (L2-hot)
// of its output's unique row and atomicAdds (16 spread atomics/address).
// Symmetric pairs (j1,j2)/(j2,j1) both read the same triangle row.
// ---------------------------------------------------------------------------
__global__ void __launch_bounds__(256) reduce_kernel(float* __restrict__ out) {
    const int ig = blockIdx.x % RED_IBLK;
    const int slice = blockIdx.x / RED_IBLK;
    const int i = ig * 256 + threadIdx.x;
    if (i >= NOUT) return;

    const int k = i >> 7;
    const int d = i & 127;
    int uk;
    if (k < 9) {
        uk = k;
    } else {
        int j1 = (k - 9) >> 3, j2 = (k - 9) & 7;
        int lo = j1 < j2 ? j1 : j2;
        int hi = j1 < j2 ? j2 : j1;
        uk = 9 + 8 * lo - (lo * (lo - 1)) / 2 + (hi - lo);
    }

    const float* p = g_partial + (size_t)slice * 8 * (NKU * D_F) + uk * D_F + d;
    float s0 = p[0 * NKU * D_F] + p[4 * NKU * D_F];
    float s1 = p[1 * NKU * D_F] + p[5 * NKU * D_F];
    float s2 = p[2 * NKU * D_F] + p[6 * NKU * D_F];
    float s3 = p[3 * NKU * D_F] + p[7 * NKU * D_F];
    atomicAdd(out + i, ((s0 + s1) + (s2 + s3)) * (1.0f / (float)V_NODES));
}

// ---------------------------------------------------------------------------
extern "C" void kernel_launch(void* const* d_in, const int* in_sizes, int n_in,
                              void* d_out, int out_size) {
    const float* W = (const float*)d_in[0];
    const float* f = (const float*)d_in[1];
    float* out = (float*)d_out;

    deg_tile_kernel<<<NTRI, 512>>>(W, out);
    scat_kernel<<<NBLK, 256>>>(f);
    reduce_kernel<<<RED_IBLK * RED_SLICES, 256>>>(out);
}